// round 12
// baseline (speedup 1.0000x reference)
#include <cuda_runtime.h>
#include <cuda_bf16.h>

#define MARGIN 1.0f
#define WARPS_PER_BLOCK 8
#define THREADS_PER_BLOCK (WARPS_PER_BLOCK * 32)
#define ROWS_PER_WARP 2
#define ROWS_PER_BLOCK (WARPS_PER_BLOCK * ROWS_PER_WARP)

// C = 1000 floats per row = 250 float4 per row (4000 bytes, 16B aligned rows)
#define C_CLASSES 1000
#define C_VEC4 250   // 1000 / 4

__device__ __forceinline__ float row_hinge_from_regs(const float4* v, int lane,
                                                     int t_vec, int t_sub, int t_lane) {
    float vmax = -3.4e38f;
    float corr = 0.0f;
    #pragma unroll
    for (int i = 0; i < 8; i++) {
        const int f = lane + (i << 5);         // raw index (not clamped)
        float4 vv = v[i];
        float m;
        if (f == t_vec) {                       // f>=250 can never match t_vec<=249
            float vals[4] = {vv.x, vv.y, vv.z, vv.w};
            corr = vals[t_sub];
            vals[t_sub] = -3.4e38f;
            m = fmaxf(fmaxf(vals[0], vals[1]), fmaxf(vals[2], vals[3]));
        } else {
            m = fmaxf(fmaxf(vv.x, vv.y), fmaxf(vv.z, vv.w));
        }
        if (f < C_VEC4) vmax = fmaxf(vmax, m);
    }
    #pragma unroll
    for (int off = 16; off > 0; off >>= 1)
        vmax = fmaxf(vmax, __shfl_xor_sync(0xFFFFFFFFu, vmax, off));
    corr = __shfl_sync(0xFFFFFFFFu, corr, t_lane);
    return fmaxf(vmax - corr + MARGIN, 0.0f);
}

__global__ __launch_bounds__(THREADS_PER_BLOCK)
void hinge_main_kernel(const float* __restrict__ pred,
                       const long long* __restrict__ target,
                       float* __restrict__ out,
                       int B, float inv_B) {
    const int warp_id = threadIdx.x >> 5;
    const int lane    = threadIdx.x & 31;
    const int row0    = blockIdx.x * ROWS_PER_BLOCK + warp_id * ROWS_PER_WARP;
    const int row1    = row0 + 1;

    __shared__ float s_partial[WARPS_PER_BLOCK];

    float hinge = 0.0f;
    if (row0 < B) {
        const bool has1 = (row1 < B);

        const long long t0 = target[row0];
        const long long t1 = has1 ? target[row1] : 0;
        const int t_vec0 = (int)(t0 >> 2), t_sub0 = (int)(t0 & 3), t_lane0 = t_vec0 & 31;
        const int t_vec1 = (int)(t1 >> 2), t_sub1 = (int)(t1 & 3), t_lane1 = t_vec1 & 31;

        const float4* rowp0 = (const float4*)(pred + (size_t)row0 * C_CLASSES);
        const float4* rowp1 = (const float4*)(pred + (size_t)(has1 ? row1 : row0) * C_CLASSES);

        // ---- Phase 1: issue ALL 16 loads back-to-back (MLP = 16) ----
        // Tail indices clamped to 249 so every LDG.128 is unconditional.
        float4 a[8], b[8];
        #pragma unroll
        for (int i = 0; i < 8; i++) {
            int f = lane + (i << 5);
            f = (f < C_VEC4) ? f : (C_VEC4 - 1);
            a[i] = __ldg(&rowp0[f]);
            b[i] = __ldg(&rowp1[f]);
        }

        // ---- Phase 2: per-row hinge ----
        hinge = row_hinge_from_regs(a, lane, t_vec0, t_sub0, t_lane0);
        if (has1)
            hinge += row_hinge_from_regs(b, lane, t_vec1, t_sub1, t_lane1);
    }

    if (lane == 0) s_partial[warp_id] = hinge;
    __syncthreads();

    // block reduce (8 values) on warp 0
    if (warp_id == 0) {
        float s = (lane < WARPS_PER_BLOCK) ? s_partial[lane] : 0.0f;
        #pragma unroll
        for (int off = 4; off > 0; off >>= 1)
            s += __shfl_xor_sync(0xFFFFFFFFu, s, off);
        if (lane == 0) atomicAdd(out, s * inv_B);
    }
}

extern "C" void kernel_launch(void* const* d_in, const int* in_sizes, int n_in,
                              void* d_out, int out_size) {
    const float*     pred   = (const float*)d_in[0];
    const long long* target = (const long long*)d_in[1];
    float*           out    = (float*)d_out;

    const int B = in_sizes[1];          // target has B elements
    const float inv_B = 1.0f / (float)B;

    // zero the scalar accumulator via a graph memset node
    cudaMemsetAsync(out, 0, sizeof(float));

    const int blocks = (B + ROWS_PER_BLOCK - 1) / ROWS_PER_BLOCK;
    hinge_main_kernel<<<blocks, THREADS_PER_BLOCK>>>(pred, target, out, B, inv_B);
}

// round 13
// speedup vs baseline: 1.0144x; 1.0144x over previous
#include <cuda_runtime.h>
#include <cuda_bf16.h>

#define MARGIN 1.0f
#define WARPS_PER_BLOCK 8
#define THREADS_PER_BLOCK (WARPS_PER_BLOCK * 32)
#define ROWS_PER_WARP 2
#define ROWS_PER_BLOCK (WARPS_PER_BLOCK * ROWS_PER_WARP)

// C = 1000 floats per row = 250 float4 per row (4000 bytes, 16B aligned rows)
#define C_CLASSES 1000
#define C_VEC4 250   // 1000 / 4

__device__ __forceinline__ float row_hinge_from_regs(const float4* v, int lane,
                                                     int t_vec, int t_sub, int t_lane) {
    float vmax = -3.4e38f;
    float corr = 0.0f;
    #pragma unroll
    for (int i = 0; i < 8; i++) {
        const int f = lane + (i << 5);         // raw index (not clamped)
        float4 vv = v[i];
        float m;
        if (f == t_vec) {                       // f>=250 can never match t_vec<=249
            float vals[4] = {vv.x, vv.y, vv.z, vv.w};
            corr = vals[t_sub];
            vals[t_sub] = -3.4e38f;
            m = fmaxf(fmaxf(vals[0], vals[1]), fmaxf(vals[2], vals[3]));
        } else {
            m = fmaxf(fmaxf(vv.x, vv.y), fmaxf(vv.z, vv.w));
        }
        if (f < C_VEC4) vmax = fmaxf(vmax, m);
    }
    #pragma unroll
    for (int off = 16; off > 0; off >>= 1)
        vmax = fmaxf(vmax, __shfl_xor_sync(0xFFFFFFFFu, vmax, off));
    corr = __shfl_sync(0xFFFFFFFFu, corr, t_lane);
    return fmaxf(vmax - corr + MARGIN, 0.0f);
}

__global__ __launch_bounds__(THREADS_PER_BLOCK)
void hinge_main_kernel(const float* __restrict__ pred,
                       const long long* __restrict__ target,
                       float* __restrict__ out,
                       int B, float inv_B) {
    const int warp_id = threadIdx.x >> 5;
    const int lane    = threadIdx.x & 31;
    const int row0    = blockIdx.x * ROWS_PER_BLOCK + warp_id * ROWS_PER_WARP;
    const int row1    = row0 + 1;

    __shared__ float s_partial[WARPS_PER_BLOCK];

    float hinge = 0.0f;
    if (row0 < B) {
        const bool has1 = (row1 < B);

        const long long t0 = target[row0];
        const long long t1 = has1 ? target[row1] : 0;
        const int t_vec0 = (int)(t0 >> 2), t_sub0 = (int)(t0 & 3), t_lane0 = t_vec0 & 31;
        const int t_vec1 = (int)(t1 >> 2), t_sub1 = (int)(t1 & 3), t_lane1 = t_vec1 & 31;

        const float4* rowp0 = (const float4*)(pred + (size_t)row0 * C_CLASSES);
        const float4* rowp1 = (const float4*)(pred + (size_t)(has1 ? row1 : row0) * C_CLASSES);

        // ---- Phase 1: issue ALL 16 loads back-to-back (MLP = 16) ----
        // Tail indices clamped to 249 so every LDG.128 is unconditional.
        float4 a[8], b[8];
        #pragma unroll
        for (int i = 0; i < 8; i++) {
            int f = lane + (i << 5);
            f = (f < C_VEC4) ? f : (C_VEC4 - 1);
            a[i] = __ldg(&rowp0[f]);
            b[i] = __ldg(&rowp1[f]);
        }

        // ---- Phase 2: per-row hinge ----
        hinge = row_hinge_from_regs(a, lane, t_vec0, t_sub0, t_lane0);
        if (has1)
            hinge += row_hinge_from_regs(b, lane, t_vec1, t_sub1, t_lane1);
    }

    if (lane == 0) s_partial[warp_id] = hinge;
    __syncthreads();

    // block reduce (8 values) on warp 0
    if (warp_id == 0) {
        float s = (lane < WARPS_PER_BLOCK) ? s_partial[lane] : 0.0f;
        #pragma unroll
        for (int off = 4; off > 0; off >>= 1)
            s += __shfl_xor_sync(0xFFFFFFFFu, s, off);
        if (lane == 0) atomicAdd(out, s * inv_B);
    }
}

extern "C" void kernel_launch(void* const* d_in, const int* in_sizes, int n_in,
                              void* d_out, int out_size) {
    const float*     pred   = (const float*)d_in[0];
    const long long* target = (const long long*)d_in[1];
    float*           out    = (float*)d_out;

    const int B = in_sizes[1];          // target has B elements
    const float inv_B = 1.0f / (float)B;

    // zero the scalar accumulator via a graph memset node
    cudaMemsetAsync(out, 0, sizeof(float));

    const int blocks = (B + ROWS_PER_BLOCK - 1) / ROWS_PER_BLOCK;
    hinge_main_kernel<<<blocks, THREADS_PER_BLOCK>>>(pred, target, out, B, inv_B);
}

// round 14
// speedup vs baseline: 1.0436x; 1.0288x over previous
#include <cuda_runtime.h>
#include <cuda_bf16.h>

#define MARGIN 1.0f
#define WARPS_PER_BLOCK 8
#define THREADS_PER_BLOCK (WARPS_PER_BLOCK * 32)
#define ROWS_PER_WARP 2
#define ROWS_PER_BLOCK (WARPS_PER_BLOCK * ROWS_PER_WARP)

// C = 1000 floats per row = 250 float4 per row (4000 bytes, 16B aligned rows)
#define C_CLASSES 1000
#define C_VEC4 250   // 1000 / 4

__device__ __forceinline__ float row_hinge_from_regs(const float4* v, int lane,
                                                     int t_vec, int t_sub, int t_lane) {
    float vmax = -3.4e38f;
    float corr = 0.0f;
    #pragma unroll
    for (int i = 0; i < 8; i++) {
        const int f = lane + (i << 5);         // raw index (not clamped)
        float4 vv = v[i];
        float m;
        if (f == t_vec) {                       // f>=250 can never match t_vec<=249
            float vals[4] = {vv.x, vv.y, vv.z, vv.w};
            corr = vals[t_sub];
            vals[t_sub] = -3.4e38f;
            m = fmaxf(fmaxf(vals[0], vals[1]), fmaxf(vals[2], vals[3]));
        } else {
            m = fmaxf(fmaxf(vv.x, vv.y), fmaxf(vv.z, vv.w));
        }
        if (f < C_VEC4) vmax = fmaxf(vmax, m);
    }
    #pragma unroll
    for (int off = 16; off > 0; off >>= 1)
        vmax = fmaxf(vmax, __shfl_xor_sync(0xFFFFFFFFu, vmax, off));
    corr = __shfl_sync(0xFFFFFFFFu, corr, t_lane);
    return fmaxf(vmax - corr + MARGIN, 0.0f);
}

__global__ __launch_bounds__(THREADS_PER_BLOCK)
void hinge_main_kernel(const float* __restrict__ pred,
                       const long long* __restrict__ target,
                       float* __restrict__ out,
                       int B, float inv_B) {
    const int warp_id = threadIdx.x >> 5;
    const int lane    = threadIdx.x & 31;
    const int row0    = blockIdx.x * ROWS_PER_BLOCK + warp_id * ROWS_PER_WARP;
    const int row1    = row0 + 1;

    __shared__ float s_partial[WARPS_PER_BLOCK];

    float hinge = 0.0f;
    if (row0 < B) {
        const bool has1 = (row1 < B);

        const long long t0 = target[row0];
        const long long t1 = has1 ? target[row1] : 0;
        const int t_vec0 = (int)(t0 >> 2), t_sub0 = (int)(t0 & 3), t_lane0 = t_vec0 & 31;
        const int t_vec1 = (int)(t1 >> 2), t_sub1 = (int)(t1 & 3), t_lane1 = t_vec1 & 31;

        const float4* rowp0 = (const float4*)(pred + (size_t)row0 * C_CLASSES);
        const float4* rowp1 = (const float4*)(pred + (size_t)(has1 ? row1 : row0) * C_CLASSES);

        // ---- Phase 1: issue ALL 16 loads back-to-back (MLP = 16) ----
        // Tail indices clamped to 249 so every LDG.128 is unconditional.
        float4 a[8], b[8];
        #pragma unroll
        for (int i = 0; i < 8; i++) {
            int f = lane + (i << 5);
            f = (f < C_VEC4) ? f : (C_VEC4 - 1);
            a[i] = __ldg(&rowp0[f]);
            b[i] = __ldg(&rowp1[f]);
        }

        // ---- Phase 2: per-row hinge ----
        hinge = row_hinge_from_regs(a, lane, t_vec0, t_sub0, t_lane0);
        if (has1)
            hinge += row_hinge_from_regs(b, lane, t_vec1, t_sub1, t_lane1);
    }

    if (lane == 0) s_partial[warp_id] = hinge;
    __syncthreads();

    // block reduce (8 values) on warp 0
    if (warp_id == 0) {
        float s = (lane < WARPS_PER_BLOCK) ? s_partial[lane] : 0.0f;
        #pragma unroll
        for (int off = 4; off > 0; off >>= 1)
            s += __shfl_xor_sync(0xFFFFFFFFu, s, off);
        if (lane == 0) atomicAdd(out, s * inv_B);
    }
}

extern "C" void kernel_launch(void* const* d_in, const int* in_sizes, int n_in,
                              void* d_out, int out_size) {
    const float*     pred   = (const float*)d_in[0];
    const long long* target = (const long long*)d_in[1];
    float*           out    = (float*)d_out;

    const int B = in_sizes[1];          // target has B elements
    const float inv_B = 1.0f / (float)B;

    // zero the scalar accumulator via a graph memset node
    cudaMemsetAsync(out, 0, sizeof(float));

    const int blocks = (B + ROWS_PER_BLOCK - 1) / ROWS_PER_BLOCK;
    hinge_main_kernel<<<blocks, THREADS_PER_BLOCK>>>(pred, target, out, B, inv_B);
}